// round 14
// baseline (speedup 1.0000x reference)
#include <cuda_runtime.h>
#include <cuda_bf16.h>
#include <cstdint>

// Problem constants
#define B_   2
#define T_   2048
#define D_   1024
#define H_   16
#define HD_  64
#define M_   (B_ * T_)       // 4096
#define NQKV (3 * D_)        // 3072
#define K_   D_              // 1024

// ---------------------------------------------------------------------------
// Scratch (__device__ globals: allocation-free rule)
// ---------------------------------------------------------------------------
__device__ __nv_bfloat16 g_xh[M_ * D_],    g_xl[M_ * D_];
__device__ __nv_bfloat16 g_wqh[NQKV * D_], g_wql[NQKV * D_];
__device__ __nv_bfloat16 g_wph[D_ * D_],   g_wpl[D_ * D_];
__device__ __nv_bfloat16 g_Qh[M_ * D_], g_Ql[M_ * D_];
__device__ __nv_bfloat16 g_Kh[M_ * D_], g_Kl[M_ * D_];
__device__ __nv_bfloat16 g_Vh[M_ * D_], g_Vl[M_ * D_];
__device__ __nv_bfloat16 g_oh[M_ * D_], g_ol[M_ * D_];

// ---------------------------------------------------------------------------
// Base-ISA tensor-core helpers (compute_103-safe: NO tcgen05)
// ---------------------------------------------------------------------------
__device__ __forceinline__ uint32_t smem_to_u32(const void* p) {
    uint32_t a;
    asm("{ .reg .u64 t; cvta.to.shared.u64 t, %1; cvt.u32.u64 %0, t; }"
        : "=r"(a) : "l"(p));
    return a;
}
__device__ __forceinline__ void ldsm4(uint32_t* r, uint32_t addr) {
    asm volatile("ldmatrix.sync.aligned.m8n8.x4.shared.b16 {%0,%1,%2,%3}, [%4];"
        : "=r"(r[0]), "=r"(r[1]), "=r"(r[2]), "=r"(r[3]) : "r"(addr));
}
__device__ __forceinline__ void ldsm4t(uint32_t* r, uint32_t addr) {
    asm volatile("ldmatrix.sync.aligned.m8n8.x4.trans.shared.b16 {%0,%1,%2,%3}, [%4];"
        : "=r"(r[0]), "=r"(r[1]), "=r"(r[2]), "=r"(r[3]) : "r"(addr));
}
__device__ __forceinline__ void mma16816(float* d, const uint32_t* a, const uint32_t* b) {
    asm volatile(
        "mma.sync.aligned.m16n8k16.row.col.f32.bf16.bf16.f32 "
        "{%0,%1,%2,%3}, {%4,%5,%6,%7}, {%8,%9}, {%0,%1,%2,%3};"
        : "+f"(d[0]), "+f"(d[1]), "+f"(d[2]), "+f"(d[3])
        : "r"(a[0]), "r"(a[1]), "r"(a[2]), "r"(a[3]), "r"(b[0]), "r"(b[1]));
}
#define CP_ASYNC16(s, g) \
    asm volatile("cp.async.cg.shared.global [%0], [%1], 16;" :: "r"(s), "l"(g))
#define CP_COMMIT() asm volatile("cp.async.commit_group;" ::: "memory")
#define CP_WAIT1()  asm volatile("cp.async.wait_group 1;" ::: "memory")
#define CP_WAIT0()  asm volatile("cp.async.wait_group 0;" ::: "memory")

__device__ __forceinline__ void split2(float x, float y, uint32_t& hi, uint32_t& lo) {
    __nv_bfloat16 hx = __float2bfloat16(x), hy = __float2bfloat16(y);
    __nv_bfloat162 hv(hx, hy);
    __nv_bfloat162 lv(__float2bfloat16(x - __bfloat162float(hx)),
                      __float2bfloat16(y - __bfloat162float(hy)));
    hi = *reinterpret_cast<uint32_t*>(&hv);
    lo = *reinterpret_cast<uint32_t*>(&lv);
}

// ---------------------------------------------------------------------------
// fp32 -> bf16 hi/lo split kernels.  SRC: 0=x, 1=W_qkv, 2=W_proj
// ---------------------------------------------------------------------------
template <int SRC>
__global__ __launch_bounds__(256)
void split_kernel(const float* __restrict__ src, int n)
{
    __nv_bfloat16 *h, *l;
    if      (SRC == 0) { h = g_xh;  l = g_xl;  }
    else if (SRC == 1) { h = g_wqh; l = g_wql; }
    else               { h = g_wph; l = g_wpl; }

    int i = (blockIdx.x * 256 + threadIdx.x) * 4;
    if (i >= n) return;
    float4 v = *(const float4*)(src + i);
    uint32_t h0, l0, h1, l1;
    split2(v.x, v.y, h0, l0);
    split2(v.z, v.w, h1, l1);
    uint32_t* hp = (uint32_t*)(h + i);
    uint32_t* lp = (uint32_t*)(l + i);
    hp[0] = h0; hp[1] = h1;
    lp[0] = l0; lp[1] = l1;
}

// ---------------------------------------------------------------------------
// Warp-MMA GEMM (HMMA bf16, 3-term split): C = A @ W^T + bias.  (unchanged,
// measured 250us / tensor=51% / regs=128 / 2 CTAs per SM)
// ---------------------------------------------------------------------------
#define ROWB        80u
#define TILE_BYTES  (128u * ROWB)
#define STAGE_BYTES (4u * TILE_BYTES)
#define GEMM_SMEM   (2 * (int)STAGE_BYTES)
#define NCH         (K_ / 32)

__device__ __forceinline__ void load_stage(
    uint32_t sbase,
    const __nv_bfloat16* __restrict__ Ah, const __nv_bfloat16* __restrict__ Al,
    const __nv_bfloat16* __restrict__ Bh, const __nv_bfloat16* __restrict__ Bl,
    int m0, int n0, int k0, int tid)
{
#pragma unroll
    for (int i = 0; i < 8; ++i) {
        const int arr = i >> 1;
        const int row = ((i & 1) << 6) + (tid >> 2);
        const int ck  = tid & 3;
        const __nv_bfloat16* src = (arr == 0) ? Ah : (arr == 1) ? Al
                                  : (arr == 2) ? Bh : Bl;
        const int grow = ((arr < 2) ? m0 : n0) + row;
        const void* g = (const char*)(src + (size_t)grow * K_ + k0) + ck * 16;
        uint32_t s = sbase + (uint32_t)arr * TILE_BYTES
                           + (uint32_t)row * ROWB + (uint32_t)ck * 16u;
        CP_ASYNC16(s, g);
    }
}

template <int MODE>
__global__ __launch_bounds__(256, 2)
void gemm_wm(const float* __restrict__ bias, float* __restrict__ out)
{
    extern __shared__ char smem[];

    const __nv_bfloat16* Ah = (MODE == 0) ? g_xh  : g_oh;
    const __nv_bfloat16* Al = (MODE == 0) ? g_xl  : g_ol;
    const __nv_bfloat16* Bh = (MODE == 0) ? g_wqh : g_wph;
    const __nv_bfloat16* Bl = (MODE == 0) ? g_wql : g_wpl;

    const int tid    = threadIdx.x;
    const int wid    = tid >> 5;
    const int lane   = tid & 31;
    const int m0     = blockIdx.y << 7;
    const int n0     = blockIdx.x << 7;
    const int warp_m = (wid >> 1) * 32;
    const int warp_n = (wid & 1) * 64;
    const uint32_t sb = smem_to_u32(smem);

    const int sub = lane >> 3, rin = lane & 7;
    const uint32_t a_ro = (uint32_t)((sub & 1) * 8 + rin) * ROWB
                        + (uint32_t)(sub >> 1) * 16u;
    const uint32_t b_ro = (uint32_t)((sub >> 1) * 8 + rin) * ROWB
                        + (uint32_t)(sub & 1) * 16u;

    float acc[2][8][4];
#pragma unroll
    for (int mt = 0; mt < 2; ++mt)
#pragma unroll
        for (int nt = 0; nt < 8; ++nt)
#pragma unroll
            for (int q = 0; q < 4; ++q) acc[mt][nt][q] = 0.f;

    load_stage(sb, Ah, Al, Bh, Bl, m0, n0, 0, tid);
    CP_COMMIT();

    for (int ch = 0; ch < NCH; ++ch) {
        const uint32_t st = sb + (uint32_t)(ch & 1) * STAGE_BYTES;
        __syncthreads();
        if (ch + 1 < NCH) {
            load_stage(sb + (uint32_t)((ch + 1) & 1) * STAGE_BYTES,
                       Ah, Al, Bh, Bl, m0, n0, (ch + 1) * 32, tid);
            CP_COMMIT();
            CP_WAIT1();
        } else {
            CP_WAIT0();
        }
        __syncthreads();

#pragma unroll
        for (int ks = 0; ks < 2; ++ks) {
            uint32_t ah[2][4], alr[2][4];
#pragma unroll
            for (int mt = 0; mt < 2; ++mt) {
                uint32_t ab = st + (uint32_t)(warp_m + mt * 16) * ROWB
                                 + a_ro + (uint32_t)ks * 32u;
                ldsm4(ah[mt],  ab);
                ldsm4(alr[mt], ab + TILE_BYTES);
            }
#pragma unroll
            for (int ng = 0; ng < 4; ++ng) {
                uint32_t bh[4], blr[4];
                uint32_t bbadr = st + 2u * TILE_BYTES
                               + (uint32_t)(warp_n + ng * 16) * ROWB
                               + b_ro + (uint32_t)ks * 32u;
                ldsm4(bh,  bbadr);
                ldsm4(blr, bbadr + TILE_BYTES);
#pragma unroll
                for (int mt = 0; mt < 2; ++mt)
#pragma unroll
                    for (int hf = 0; hf < 2; ++hf) {
                        float* d = acc[mt][ng * 2 + hf];
                        mma16816(d, ah[mt],  bh  + hf * 2);
                        mma16816(d, ah[mt],  blr + hf * 2);
                        mma16816(d, alr[mt], bh  + hf * 2);
                    }
            }
        }
    }

    const int qrow = lane >> 2;
    const int qcol = (lane & 3) * 2;
#pragma unroll
    for (int mt = 0; mt < 2; ++mt)
#pragma unroll
        for (int rr = 0; rr < 2; ++rr) {
            const int m  = m0 + warp_m + mt * 16 + qrow + rr * 8;
            const int bb = m >> 11;
            const int t  = m & (T_ - 1);
#pragma unroll
            for (int nt = 0; nt < 8; ++nt) {
                const int n = n0 + warp_n + nt * 8 + qcol;
                float vx = acc[mt][nt][rr * 2 + 0] + bias[n];
                float vy = acc[mt][nt][rr * 2 + 1] + bias[n + 1];
                if (MODE == 0) {
                    const int part = n >> 10;       // 0=Q 1=K 2=V
                    const int c    = n & (D_ - 1);
                    const int h    = c >> 6;
                    const int d    = c & (HD_ - 1);
                    __nv_bfloat16 *dh, *dl;
                    if      (part == 0) { dh = g_Qh; dl = g_Ql; }
                    else if (part == 1) { dh = g_Kh; dl = g_Kl; }
                    else                { dh = g_Vh; dl = g_Vl; }
                    size_t idx = ((size_t)(bb * H_ + h) * T_ + t) * HD_ + d;
                    uint32_t hi, lo;
                    split2(vx, vy, hi, lo);
                    *(uint32_t*)(dh + idx) = hi;
                    *(uint32_t*)(dl + idx) = lo;
                } else {
                    float2 v; v.x = vx; v.y = vy;
                    *(float2*)(out + (size_t)m * D_ + n) = v;
                }
            }
        }
}

// ---------------------------------------------------------------------------
// HMMA flash-attention (causal), 2 Q-tiles per CTA: 256 queries of one (b,h)
// share each KV block load -> KV L2 traffic, cp.async issue and barrier count
// per unit MMA all drop ~47% vs the 128-query version. 8 warps x 16 rows per
// tile; KV blocks of 64, double-buffered; 3-term bf16 split throughout.
// ---------------------------------------------------------------------------
#define AROWB        144u
#define KVT_BYTES    (64u * AROWB)          // 9216
#define ATT_STAGE    (4u * KVT_BYTES)       // 36864 (Kh,Kl,Vh,Vl)
#define Q_REGION     (2u * 256u * AROWB)    // 73728 (Qh | Ql, 256 rows)
#define ATT_SMEM     (int)(Q_REGION + 2u * ATT_STAGE)   // 147456

__device__ __forceinline__ void attn_load_kv(uint32_t sk, size_t base, int kb0, int tid)
{
#pragma unroll
    for (int i = 0; i < 8; ++i) {
        const int arr = i >> 1;                     // 0 Kh,1 Kl,2 Vh,3 Vl
        const int row = ((i & 1) << 5) + (tid >> 3);
        const int ck  = tid & 7;
        const __nv_bfloat16* src = (arr == 0) ? g_Kh : (arr == 1) ? g_Kl
                                  : (arr == 2) ? g_Vh : g_Vl;
        const void* g = src + base + (size_t)(kb0 + row) * HD_ + ck * 8;
        uint32_t s = sk + (uint32_t)arr * KVT_BYTES
                        + (uint32_t)row * AROWB + (uint32_t)ck * 16u;
        CP_ASYNC16(s, g);
    }
}

__global__ __launch_bounds__(256)
void attn_wm()
{
    extern __shared__ char smem[];
    const uint32_t sQ   = smem_to_u32(smem);
    const uint32_t sKV0 = sQ + Q_REGION;

    const int tid    = threadIdx.x;
    const int wid    = tid >> 5;
    const int lane   = tid & 31;
    const int qb     = (int)gridDim.x - 1 - (int)blockIdx.x;   // heavy first
    const int bh     = blockIdx.y;
    const int q0     = qb << 8;                 // 256 queries per CTA
    const size_t base = (size_t)bh * (T_ * HD_);
    const int warp_m = wid * 16;
    const int nblk   = 4 * (qb + 1);
    const float scale = 0.125f;

    const int sub = lane >> 3, rin = lane & 7;
    const uint32_t a_ro = (uint32_t)((sub & 1) * 8 + rin) * AROWB
                        + (uint32_t)(sub >> 1) * 16u;
    const uint32_t b_ro = (uint32_t)((sub >> 1) * 8 + rin) * AROWB
                        + (uint32_t)(sub & 1) * 16u;

    // ---- Q load: 256 rows, hi at sQ, lo at sQ + 256*AROWB ----
#pragma unroll
    for (int i = 0; i < 16; ++i) {
        const int arr = i >> 3;                     // 0 Qh, 1 Ql
        const int row = ((i & 7) << 5) + (tid >> 3);
        const int ck  = tid & 7;
        const __nv_bfloat16* src = arr ? g_Ql : g_Qh;
        const void* g = src + base + (size_t)(q0 + row) * HD_ + ck * 8;
        uint32_t s = sQ + (uint32_t)arr * (256u * AROWB)
                        + (uint32_t)row * AROWB + (uint32_t)ck * 16u;
        CP_ASYNC16(s, g);
    }
    CP_COMMIT();                                    // group: Q
    attn_load_kv(sKV0, base, 0, tid);               // KV block 0 -> buffer 0
    CP_COMMIT();                                    // group: KV0
    CP_WAIT1();                                     // Q complete
    __syncthreads();

    // Q fragments for both tiles (resident; Q smem not touched afterwards)
    uint32_t qfh[2][4][4], qfl[2][4][4];
#pragma unroll
    for (int t = 0; t < 2; ++t)
#pragma unroll
        for (int ks = 0; ks < 4; ++ks) {
            uint32_t ab = sQ + (uint32_t)(t * 128 + warp_m) * AROWB
                             + a_ro + (uint32_t)ks * 32u;
            ldsm4(qfh[t][ks], ab);
            ldsm4(qfl[t][ks], ab + 256u * AROWB);
        }

    float oacc[2][8][4];
#pragma unroll
    for (int t = 0; t < 2; ++t)
#pragma unroll
        for (int nt = 0; nt < 8; ++nt)
#pragma unroll
            for (int q = 0; q < 4; ++q) oacc[t][nt][q] = 0.f;
    float mrow[2][2], lrow[2][2];
#pragma unroll
    for (int t = 0; t < 2; ++t) {
        mrow[t][0] = -1e30f; mrow[t][1] = -1e30f;
        lrow[t][0] = 0.f;    lrow[t][1] = 0.f;
    }

    const int qrow = lane >> 2;
    const int qcol = (lane & 3) * 2;

    for (int jb = 0; jb < nblk; ++jb) {
        const uint32_t st = sKV0 + (uint32_t)(jb & 1) * ATT_STAGE;
        const int kb0 = jb << 6;
        __syncthreads();                            // all warps done w/ other buf
        if (jb + 1 < nblk) {
            attn_load_kv(sKV0 + (uint32_t)((jb + 1) & 1) * ATT_STAGE,
                         base, (jb + 1) << 6, tid);
            CP_COMMIT();
            CP_WAIT1();
        } else {
            CP_WAIT0();
        }
        __syncthreads();

#pragma unroll
        for (int t = 0; t < 2; ++t) {
            const int tq0   = q0 + t * 128;
            const int wlast = tq0 + warp_m + 15;
            if (kb0 > wlast) continue;              // warp-uniform causal skip
            const int rg0 = tq0 + warp_m + qrow;

            // ---- S = Q K^T ----
            float s[8][4];
#pragma unroll
            for (int nt = 0; nt < 8; ++nt)
#pragma unroll
                for (int q = 0; q < 4; ++q) s[nt][q] = 0.f;

#pragma unroll
            for (int ntile = 0; ntile < 4; ++ntile) {
                if (kb0 + ntile * 16 > wlast) break;
#pragma unroll
                for (int ks = 0; ks < 4; ++ks) {
                    uint32_t kh[4], kl[4];
                    uint32_t ad = st + (uint32_t)(ntile * 16) * AROWB
                                     + b_ro + (uint32_t)ks * 32u;
                    ldsm4(kh, ad);
                    ldsm4(kl, ad + KVT_BYTES);
#pragma unroll
                    for (int hf = 0; hf < 2; ++hf) {
                        float* d = s[ntile * 2 + hf];
                        mma16816(d, qfh[t][ks], kh + hf * 2);
                        mma16816(d, qfh[t][ks], kl + hf * 2);
                        mma16816(d, qfl[t][ks], kh + hf * 2);
                    }
                }
            }

            // ---- causal mask (near-diagonal blocks) ----
            if (kb0 + 63 > tq0 + warp_m) {
#pragma unroll
                for (int nt = 0; nt < 8; ++nt) {
                    int cg = kb0 + nt * 8 + qcol;
                    if (cg     > rg0)     s[nt][0] = -1e30f;
                    if (cg + 1 > rg0)     s[nt][1] = -1e30f;
                    if (cg     > rg0 + 8) s[nt][2] = -1e30f;
                    if (cg + 1 > rg0 + 8) s[nt][3] = -1e30f;
                }
            }

            // ---- row max, rescale O ----
            float mx0 = -1e30f, mx1 = -1e30f;
#pragma unroll
            for (int nt = 0; nt < 8; ++nt) {
                mx0 = fmaxf(mx0, fmaxf(s[nt][0], s[nt][1]));
                mx1 = fmaxf(mx1, fmaxf(s[nt][2], s[nt][3]));
            }
            mx0 = fmaxf(mx0, __shfl_xor_sync(0xffffffffu, mx0, 1));
            mx0 = fmaxf(mx0, __shfl_xor_sync(0xffffffffu, mx0, 2));
            mx1 = fmaxf(mx1, __shfl_xor_sync(0xffffffffu, mx1, 1));
            mx1 = fmaxf(mx1, __shfl_xor_sync(0xffffffffu, mx1, 2));
            float mn0 = fmaxf(mrow[t][0], mx0 * scale);
            float mn1 = fmaxf(mrow[t][1], mx1 * scale);
            float f0 = __expf(mrow[t][0] - mn0);
            float f1 = __expf(mrow[t][1] - mn1);
            mrow[t][0] = mn0; mrow[t][1] = mn1;
#pragma unroll
            for (int nt = 0; nt < 8; ++nt) {
                oacc[t][nt][0] *= f0; oacc[t][nt][1] *= f0;
                oacc[t][nt][2] *= f1; oacc[t][nt][3] *= f1;
            }

            // ---- fused per-kstep softmax -> PV ----
            float sum0 = 0.f, sum1 = 0.f;
#pragma unroll
            for (int ks = 0; ks < 4; ++ks) {
                if (kb0 + ks * 16 > wlast) break;
                uint32_t ah[4], al[4];
#pragma unroll
                for (int half = 0; half < 2; ++half) {
                    const int nt = 2 * ks + half;
                    float p0 = __expf(fmaf(s[nt][0], scale, -mn0));
                    float p1 = __expf(fmaf(s[nt][1], scale, -mn0));
                    float p2 = __expf(fmaf(s[nt][2], scale, -mn1));
                    float p3 = __expf(fmaf(s[nt][3], scale, -mn1));
                    sum0 += p0 + p1;
                    sum1 += p2 + p3;
                    split2(p0, p1, ah[half * 2 + 0], al[half * 2 + 0]);
                    split2(p2, p3, ah[half * 2 + 1], al[half * 2 + 1]);
                }
#pragma unroll
                for (int dnt = 0; dnt < 4; ++dnt) {
                    uint32_t vh[4], vl[4];
                    uint32_t ad = st + 2u * KVT_BYTES
                                + (uint32_t)(ks * 16) * AROWB
                                + a_ro + (uint32_t)dnt * 32u;
                    ldsm4t(vh, ad);
                    ldsm4t(vl, ad + KVT_BYTES);
#pragma unroll
                    for (int hf = 0; hf < 2; ++hf) {
                        float* d = oacc[t][dnt * 2 + hf];
                        mma16816(d, ah, vh + hf * 2);
                        mma16816(d, al, vh + hf * 2);
                        mma16816(d, ah, vl + hf * 2);
                    }
                }
            }
            sum0 += __shfl_xor_sync(0xffffffffu, sum0, 1);
            sum0 += __shfl_xor_sync(0xffffffffu, sum0, 2);
            sum1 += __shfl_xor_sync(0xffffffffu, sum1, 1);
            sum1 += __shfl_xor_sync(0xffffffffu, sum1, 2);
            lrow[t][0] = lrow[t][0] * f0 + sum0;
            lrow[t][1] = lrow[t][1] * f1 + sum1;
        }
    }

    // ---- epilogue: both tiles ----
    const int bb = bh >> 4;
    const int h  = bh & 15;
#pragma unroll
    for (int t = 0; t < 2; ++t) {
        const float inv0 = 1.0f / lrow[t][0];
        const float inv1 = 1.0f / lrow[t][1];
        const int t0 = q0 + t * 128 + warp_m + qrow;
#pragma unroll
        for (int nt = 0; nt < 8; ++nt) {
            const int d = nt * 8 + qcol;
            uint32_t hi, lo;
            size_t i0 = (size_t)(bb * T_ + t0) * D_ + h * HD_ + d;
            split2(oacc[t][nt][0] * inv0, oacc[t][nt][1] * inv0, hi, lo);
            *(uint32_t*)(g_oh + i0) = hi;
            *(uint32_t*)(g_ol + i0) = lo;
            size_t i1 = (size_t)(bb * T_ + t0 + 8) * D_ + h * HD_ + d;
            split2(oacc[t][nt][2] * inv1, oacc[t][nt][3] * inv1, hi, lo);
            *(uint32_t*)(g_oh + i1) = hi;
            *(uint32_t*)(g_ol + i1) = lo;
        }
    }
}

// ---------------------------------------------------------------------------
// kernel_launch
// ---------------------------------------------------------------------------
extern "C" void kernel_launch(void* const* d_in, const int* in_sizes, int n_in,
                              void* d_out, int out_size)
{
    (void)in_sizes; (void)n_in; (void)out_size;
    const float* x     = (const float*)d_in[0];
    const float* Wqkv  = (const float*)d_in[1];
    const float* bqkv  = (const float*)d_in[2];
    const float* Wproj = (const float*)d_in[3];
    const float* bproj = (const float*)d_in[4];
    float* out = (float*)d_out;

    cudaFuncSetAttribute(gemm_wm<0>,
                         cudaFuncAttributeMaxDynamicSharedMemorySize, GEMM_SMEM);
    cudaFuncSetAttribute(gemm_wm<1>,
                         cudaFuncAttributeMaxDynamicSharedMemorySize, GEMM_SMEM);
    cudaFuncSetAttribute(attn_wm,
                         cudaFuncAttributeMaxDynamicSharedMemorySize, ATT_SMEM);

    split_kernel<0><<<(M_ * D_) / 1024, 256>>>(x, M_ * D_);
    split_kernel<1><<<(NQKV * D_) / 1024, 256>>>(Wqkv, NQKV * D_);
    split_kernel<2><<<(D_ * D_) / 1024, 256>>>(Wproj, D_ * D_);

    gemm_wm<0><<<dim3(NQKV / 128, M_ / 128), 256, GEMM_SMEM>>>(bqkv, nullptr);

    attn_wm<<<dim3(T_ / 256, B_ * H_), 256, ATT_SMEM>>>();

    gemm_wm<1><<<dim3(D_ / 128, M_ / 128), 256, GEMM_SMEM>>>(bproj, out);
}

// round 15
// speedup vs baseline: 1.0545x; 1.0545x over previous
#include <cuda_runtime.h>
#include <cuda_bf16.h>
#include <cstdint>

// Problem constants
#define B_   2
#define T_   2048
#define D_   1024
#define H_   16
#define HD_  64
#define M_   (B_ * T_)       // 4096
#define NQKV (3 * D_)        // 3072
#define K_   D_              // 1024

// ---------------------------------------------------------------------------
// Scratch (__device__ globals: allocation-free rule)
// ---------------------------------------------------------------------------
__device__ __nv_bfloat16 g_xh[M_ * D_],    g_xl[M_ * D_];
__device__ __nv_bfloat16 g_wqh[NQKV * D_], g_wql[NQKV * D_];
__device__ __nv_bfloat16 g_wph[D_ * D_],   g_wpl[D_ * D_];
__device__ __nv_bfloat16 g_Qh[M_ * D_], g_Ql[M_ * D_];
__device__ __nv_bfloat16 g_Kh[M_ * D_], g_Kl[M_ * D_];
__device__ __nv_bfloat16 g_Vh[M_ * D_], g_Vl[M_ * D_];
__device__ __nv_bfloat16 g_oh[M_ * D_], g_ol[M_ * D_];

// ---------------------------------------------------------------------------
// Base-ISA tensor-core helpers (compute_103-safe: NO tcgen05)
// ---------------------------------------------------------------------------
__device__ __forceinline__ uint32_t smem_to_u32(const void* p) {
    uint32_t a;
    asm("{ .reg .u64 t; cvta.to.shared.u64 t, %1; cvt.u32.u64 %0, t; }"
        : "=r"(a) : "l"(p));
    return a;
}
__device__ __forceinline__ void ldsm4(uint32_t* r, uint32_t addr) {
    asm volatile("ldmatrix.sync.aligned.m8n8.x4.shared.b16 {%0,%1,%2,%3}, [%4];"
        : "=r"(r[0]), "=r"(r[1]), "=r"(r[2]), "=r"(r[3]) : "r"(addr));
}
__device__ __forceinline__ void ldsm4t(uint32_t* r, uint32_t addr) {
    asm volatile("ldmatrix.sync.aligned.m8n8.x4.trans.shared.b16 {%0,%1,%2,%3}, [%4];"
        : "=r"(r[0]), "=r"(r[1]), "=r"(r[2]), "=r"(r[3]) : "r"(addr));
}
__device__ __forceinline__ void mma16816(float* d, const uint32_t* a, const uint32_t* b) {
    asm volatile(
        "mma.sync.aligned.m16n8k16.row.col.f32.bf16.bf16.f32 "
        "{%0,%1,%2,%3}, {%4,%5,%6,%7}, {%8,%9}, {%0,%1,%2,%3};"
        : "+f"(d[0]), "+f"(d[1]), "+f"(d[2]), "+f"(d[3])
        : "r"(a[0]), "r"(a[1]), "r"(a[2]), "r"(a[3]), "r"(b[0]), "r"(b[1]));
}
#define CP_ASYNC16(s, g) \
    asm volatile("cp.async.cg.shared.global [%0], [%1], 16;" :: "r"(s), "l"(g))
#define CP_COMMIT() asm volatile("cp.async.commit_group;" ::: "memory")
#define CP_WAIT1()  asm volatile("cp.async.wait_group 1;" ::: "memory")
#define CP_WAIT0()  asm volatile("cp.async.wait_group 0;" ::: "memory")

__device__ __forceinline__ void split2(float x, float y, uint32_t& hi, uint32_t& lo) {
    __nv_bfloat16 hx = __float2bfloat16(x), hy = __float2bfloat16(y);
    __nv_bfloat162 hv(hx, hy);
    __nv_bfloat162 lv(__float2bfloat16(x - __bfloat162float(hx)),
                      __float2bfloat16(y - __bfloat162float(hy)));
    hi = *reinterpret_cast<uint32_t*>(&hv);
    lo = *reinterpret_cast<uint32_t*>(&lv);
}

// ---------------------------------------------------------------------------
// Merged fp32 -> bf16 hi/lo split: one launch covers x | W_qkv | W_proj.
// Ranges (in elements): [0, 4M) x ; [4M, 7M) W_qkv ; [7M, 8M) W_proj.
// ---------------------------------------------------------------------------
#define XN   (M_ * D_)          // 4194304
#define WQN  (NQKV * D_)        // 3145728
#define WPN  (D_ * D_)          // 1048576
#define SPLIT_TOTAL (XN + WQN + WPN)

__global__ __launch_bounds__(256)
void split_all(const float* __restrict__ x, const float* __restrict__ wq,
               const float* __restrict__ wp)
{
    int i = (blockIdx.x * 256 + threadIdx.x) * 4;
    if (i >= SPLIT_TOTAL) return;

    const float* src;
    __nv_bfloat16 *h, *l;
    int off;
    if (i < XN)            { src = x;  h = g_xh;  l = g_xl;  off = i; }
    else if (i < XN + WQN) { src = wq; h = g_wqh; l = g_wql; off = i - XN; }
    else                   { src = wp; h = g_wph; l = g_wpl; off = i - XN - WQN; }

    float4 v = *(const float4*)(src + off);
    uint32_t h0, l0, h1, l1;
    split2(v.x, v.y, h0, l0);
    split2(v.z, v.w, h1, l1);
    uint32_t* hp = (uint32_t*)(h + off);
    uint32_t* lp = (uint32_t*)(l + off);
    hp[0] = h0; hp[1] = h1;
    lp[0] = l0; lp[1] = l1;
}

// ---------------------------------------------------------------------------
// Warp-MMA GEMM (HMMA bf16, 3-term split): C = A @ W^T + bias.  (unchanged,
// measured 250us / tensor=51% / regs=128 / 2 CTAs per SM)
// ---------------------------------------------------------------------------
#define ROWB        80u
#define TILE_BYTES  (128u * ROWB)
#define STAGE_BYTES (4u * TILE_BYTES)
#define GEMM_SMEM   (2 * (int)STAGE_BYTES)
#define NCH         (K_ / 32)

__device__ __forceinline__ void load_stage(
    uint32_t sbase,
    const __nv_bfloat16* __restrict__ Ah, const __nv_bfloat16* __restrict__ Al,
    const __nv_bfloat16* __restrict__ Bh, const __nv_bfloat16* __restrict__ Bl,
    int m0, int n0, int k0, int tid)
{
#pragma unroll
    for (int i = 0; i < 8; ++i) {
        const int arr = i >> 1;
        const int row = ((i & 1) << 6) + (tid >> 2);
        const int ck  = tid & 3;
        const __nv_bfloat16* src = (arr == 0) ? Ah : (arr == 1) ? Al
                                  : (arr == 2) ? Bh : Bl;
        const int grow = ((arr < 2) ? m0 : n0) + row;
        const void* g = (const char*)(src + (size_t)grow * K_ + k0) + ck * 16;
        uint32_t s = sbase + (uint32_t)arr * TILE_BYTES
                           + (uint32_t)row * ROWB + (uint32_t)ck * 16u;
        CP_ASYNC16(s, g);
    }
}

template <int MODE>
__global__ __launch_bounds__(256, 2)
void gemm_wm(const float* __restrict__ bias, float* __restrict__ out)
{
    extern __shared__ char smem[];

    const __nv_bfloat16* Ah = (MODE == 0) ? g_xh  : g_oh;
    const __nv_bfloat16* Al = (MODE == 0) ? g_xl  : g_ol;
    const __nv_bfloat16* Bh = (MODE == 0) ? g_wqh : g_wph;
    const __nv_bfloat16* Bl = (MODE == 0) ? g_wql : g_wpl;

    const int tid    = threadIdx.x;
    const int wid    = tid >> 5;
    const int lane   = tid & 31;
    const int m0     = blockIdx.y << 7;
    const int n0     = blockIdx.x << 7;
    const int warp_m = (wid >> 1) * 32;
    const int warp_n = (wid & 1) * 64;
    const uint32_t sb = smem_to_u32(smem);

    const int sub = lane >> 3, rin = lane & 7;
    const uint32_t a_ro = (uint32_t)((sub & 1) * 8 + rin) * ROWB
                        + (uint32_t)(sub >> 1) * 16u;
    const uint32_t b_ro = (uint32_t)((sub >> 1) * 8 + rin) * ROWB
                        + (uint32_t)(sub & 1) * 16u;

    float acc[2][8][4];
#pragma unroll
    for (int mt = 0; mt < 2; ++mt)
#pragma unroll
        for (int nt = 0; nt < 8; ++nt)
#pragma unroll
            for (int q = 0; q < 4; ++q) acc[mt][nt][q] = 0.f;

    load_stage(sb, Ah, Al, Bh, Bl, m0, n0, 0, tid);
    CP_COMMIT();

    for (int ch = 0; ch < NCH; ++ch) {
        const uint32_t st = sb + (uint32_t)(ch & 1) * STAGE_BYTES;
        __syncthreads();
        if (ch + 1 < NCH) {
            load_stage(sb + (uint32_t)((ch + 1) & 1) * STAGE_BYTES,
                       Ah, Al, Bh, Bl, m0, n0, (ch + 1) * 32, tid);
            CP_COMMIT();
            CP_WAIT1();
        } else {
            CP_WAIT0();
        }
        __syncthreads();

#pragma unroll
        for (int ks = 0; ks < 2; ++ks) {
            uint32_t ah[2][4], alr[2][4];
#pragma unroll
            for (int mt = 0; mt < 2; ++mt) {
                uint32_t ab = st + (uint32_t)(warp_m + mt * 16) * ROWB
                                 + a_ro + (uint32_t)ks * 32u;
                ldsm4(ah[mt],  ab);
                ldsm4(alr[mt], ab + TILE_BYTES);
            }
#pragma unroll
            for (int ng = 0; ng < 4; ++ng) {
                uint32_t bh[4], blr[4];
                uint32_t bbadr = st + 2u * TILE_BYTES
                               + (uint32_t)(warp_n + ng * 16) * ROWB
                               + b_ro + (uint32_t)ks * 32u;
                ldsm4(bh,  bbadr);
                ldsm4(blr, bbadr + TILE_BYTES);
#pragma unroll
                for (int mt = 0; mt < 2; ++mt)
#pragma unroll
                    for (int hf = 0; hf < 2; ++hf) {
                        float* d = acc[mt][ng * 2 + hf];
                        mma16816(d, ah[mt],  bh  + hf * 2);
                        mma16816(d, ah[mt],  blr + hf * 2);
                        mma16816(d, alr[mt], bh  + hf * 2);
                    }
            }
        }
    }

    const int qrow = lane >> 2;
    const int qcol = (lane & 3) * 2;
#pragma unroll
    for (int mt = 0; mt < 2; ++mt)
#pragma unroll
        for (int rr = 0; rr < 2; ++rr) {
            const int m  = m0 + warp_m + mt * 16 + qrow + rr * 8;
            const int bb = m >> 11;
            const int t  = m & (T_ - 1);
#pragma unroll
            for (int nt = 0; nt < 8; ++nt) {
                const int n = n0 + warp_n + nt * 8 + qcol;
                float vx = acc[mt][nt][rr * 2 + 0] + bias[n];
                float vy = acc[mt][nt][rr * 2 + 1] + bias[n + 1];
                if (MODE == 0) {
                    const int part = n >> 10;       // 0=Q 1=K 2=V
                    const int c    = n & (D_ - 1);
                    const int h    = c >> 6;
                    const int d    = c & (HD_ - 1);
                    __nv_bfloat16 *dh, *dl;
                    if      (part == 0) { dh = g_Qh; dl = g_Ql; }
                    else if (part == 1) { dh = g_Kh; dl = g_Kl; }
                    else                { dh = g_Vh; dl = g_Vl; }
                    size_t idx = ((size_t)(bb * H_ + h) * T_ + t) * HD_ + d;
                    uint32_t hi, lo;
                    split2(vx, vy, hi, lo);
                    *(uint32_t*)(dh + idx) = hi;
                    *(uint32_t*)(dl + idx) = lo;
                } else {
                    float2 v; v.x = vx; v.y = vy;
                    *(float2*)(out + (size_t)m * D_ + n) = v;
                }
            }
        }
}

// ---------------------------------------------------------------------------
// HMMA flash-attention (causal) — EXACT R7 build (best measured: 567.3us).
// 128 queries/CTA of one (b,h), 8 warps x 16 rows, KV blocks of 64,
// cp.async double-buffered, 3-term bf16 split, causal tile-skipping.
// ---------------------------------------------------------------------------
#define AROWB        144u
#define Q_TILE_BYTES (128u * AROWB)     // 18432
#define KVT_BYTES    (64u * AROWB)      // 9216
#define ATT_STAGE    (4u * KVT_BYTES)   // 36864
#define ATT_SMEM     (int)(2u * Q_TILE_BYTES + 2u * ATT_STAGE)  // 110592

__device__ __forceinline__ void attn_load_kv(uint32_t sk, size_t base, int kb0, int tid)
{
#pragma unroll
    for (int i = 0; i < 8; ++i) {
        const int arr = i >> 1;                     // 0 Kh,1 Kl,2 Vh,3 Vl
        const int row = ((i & 1) << 5) + (tid >> 3);
        const int ck  = tid & 7;
        const __nv_bfloat16* src = (arr == 0) ? g_Kh : (arr == 1) ? g_Kl
                                  : (arr == 2) ? g_Vh : g_Vl;
        const void* g = src + base + (size_t)(kb0 + row) * HD_ + ck * 8;
        uint32_t s = sk + (uint32_t)arr * KVT_BYTES
                        + (uint32_t)row * AROWB + (uint32_t)ck * 16u;
        CP_ASYNC16(s, g);
    }
}

__global__ __launch_bounds__(256)
void attn_wm()
{
    extern __shared__ char smem[];
    const uint32_t sb   = smem_to_u32(smem);
    const uint32_t sQ   = sb;
    const uint32_t sKV0 = sb + 2u * Q_TILE_BYTES;

    const int tid    = threadIdx.x;
    const int wid    = tid >> 5;
    const int lane   = tid & 31;
    const int qb     = (int)gridDim.x - 1 - (int)blockIdx.x;   // heavy first
    const int bh     = blockIdx.y;
    const int q0     = qb << 7;
    const size_t base = (size_t)bh * (T_ * HD_);
    const int warp_m = wid * 16;
    const int nblk   = 2 * (qb + 1);
    const int wlast  = q0 + warp_m + 15;    // last valid col for this warp
    const float scale = 0.125f;

    const int sub = lane >> 3, rin = lane & 7;
    const uint32_t a_ro = (uint32_t)((sub & 1) * 8 + rin) * AROWB
                        + (uint32_t)(sub >> 1) * 16u;
    const uint32_t b_ro = (uint32_t)((sub >> 1) * 8 + rin) * AROWB
                        + (uint32_t)(sub & 1) * 16u;

#pragma unroll
    for (int i = 0; i < 8; ++i) {
        const int arr = i >> 2;                     // 0 Qh, 1 Ql
        const int row = ((i & 3) << 5) + (tid >> 3);
        const int ck  = tid & 7;
        const __nv_bfloat16* src = arr ? g_Ql : g_Qh;
        const void* g = src + base + (size_t)(q0 + row) * HD_ + ck * 8;
        uint32_t s = sQ + (uint32_t)arr * Q_TILE_BYTES
                        + (uint32_t)row * AROWB + (uint32_t)ck * 16u;
        CP_ASYNC16(s, g);
    }
    CP_COMMIT();
    attn_load_kv(sKV0, base, 0, tid);
    CP_COMMIT();
    CP_WAIT1();
    __syncthreads();

    uint32_t qh[4][4], ql[4][4];
#pragma unroll
    for (int ks = 0; ks < 4; ++ks) {
        uint32_t ab = sQ + (uint32_t)warp_m * AROWB + a_ro + (uint32_t)ks * 32u;
        ldsm4(qh[ks], ab);
        ldsm4(ql[ks], ab + Q_TILE_BYTES);
    }

    float oacc[8][4];
#pragma unroll
    for (int nt = 0; nt < 8; ++nt)
#pragma unroll
        for (int q = 0; q < 4; ++q) oacc[nt][q] = 0.f;
    float m0r = -1e30f, m1r = -1e30f, l0r = 0.f, l1r = 0.f;

    const int qrow = lane >> 2;
    const int qcol = (lane & 3) * 2;
    const int rg0  = q0 + warp_m + qrow;

    for (int jb = 0; jb < nblk; ++jb) {
        const uint32_t st = sKV0 + (uint32_t)(jb & 1) * ATT_STAGE;
        const int kb0 = jb << 6;
        __syncthreads();
        if (jb + 1 < nblk) {
            attn_load_kv(sKV0 + (uint32_t)((jb + 1) & 1) * ATT_STAGE,
                         base, (jb + 1) << 6, tid);
            CP_COMMIT();
            CP_WAIT1();
        } else {
            CP_WAIT0();
        }
        __syncthreads();

        const bool block_dead = (kb0 > wlast);
        if (!block_dead) {
            // ---- S = Q K^T ----
            float s[8][4];
#pragma unroll
            for (int nt = 0; nt < 8; ++nt)
#pragma unroll
                for (int q = 0; q < 4; ++q) s[nt][q] = 0.f;

#pragma unroll
            for (int ntile = 0; ntile < 4; ++ntile) {
                if (kb0 + ntile * 16 > wlast) break;   // warp-uniform causal skip
#pragma unroll
                for (int ks = 0; ks < 4; ++ks) {
                    uint32_t kh[4], kl[4];
                    uint32_t ad = st + (uint32_t)(ntile * 16) * AROWB
                                     + b_ro + (uint32_t)ks * 32u;
                    ldsm4(kh, ad);
                    ldsm4(kl, ad + KVT_BYTES);
#pragma unroll
                    for (int hf = 0; hf < 2; ++hf) {
                        float* d = s[ntile * 2 + hf];
                        mma16816(d, qh[ks], kh + hf * 2);
                        mma16816(d, qh[ks], kl + hf * 2);
                        mma16816(d, ql[ks], kh + hf * 2);
                    }
                }
            }

            // ---- causal mask (near-diagonal blocks) ----
            if (kb0 + 63 > q0 + warp_m) {
#pragma unroll
                for (int nt = 0; nt < 8; ++nt) {
                    int cg = kb0 + nt * 8 + qcol;
                    if (cg     > rg0)     s[nt][0] = -1e30f;
                    if (cg + 1 > rg0)     s[nt][1] = -1e30f;
                    if (cg     > rg0 + 8) s[nt][2] = -1e30f;
                    if (cg + 1 > rg0 + 8) s[nt][3] = -1e30f;
                }
            }

            // ---- online softmax ----
            float mx0 = -1e30f, mx1 = -1e30f;
#pragma unroll
            for (int nt = 0; nt < 8; ++nt) {
                mx0 = fmaxf(mx0, fmaxf(s[nt][0], s[nt][1]));
                mx1 = fmaxf(mx1, fmaxf(s[nt][2], s[nt][3]));
            }
            mx0 = fmaxf(mx0, __shfl_xor_sync(0xffffffffu, mx0, 1));
            mx0 = fmaxf(mx0, __shfl_xor_sync(0xffffffffu, mx0, 2));
            mx1 = fmaxf(mx1, __shfl_xor_sync(0xffffffffu, mx1, 1));
            mx1 = fmaxf(mx1, __shfl_xor_sync(0xffffffffu, mx1, 2));
            float mn0 = fmaxf(m0r, mx0 * scale);
            float mn1 = fmaxf(m1r, mx1 * scale);

            uint32_t ph[8][2], pl[8][2];
            float sum0 = 0.f, sum1 = 0.f;
#pragma unroll
            for (int nt = 0; nt < 8; ++nt) {
                float p0 = __expf(fmaf(s[nt][0], scale, -mn0));
                float p1 = __expf(fmaf(s[nt][1], scale, -mn0));
                float p2 = __expf(fmaf(s[nt][2], scale, -mn1));
                float p3 = __expf(fmaf(s[nt][3], scale, -mn1));
                sum0 += p0 + p1;
                sum1 += p2 + p3;
                split2(p0, p1, ph[nt][0], pl[nt][0]);
                split2(p2, p3, ph[nt][1], pl[nt][1]);
            }
            sum0 += __shfl_xor_sync(0xffffffffu, sum0, 1);
            sum0 += __shfl_xor_sync(0xffffffffu, sum0, 2);
            sum1 += __shfl_xor_sync(0xffffffffu, sum1, 1);
            sum1 += __shfl_xor_sync(0xffffffffu, sum1, 2);

            float f0 = __expf(m0r - mn0);
            float f1 = __expf(m1r - mn1);
            l0r = l0r * f0 + sum0;
            l1r = l1r * f1 + sum1;
            m0r = mn0; m1r = mn1;
#pragma unroll
            for (int nt = 0; nt < 8; ++nt) {
                oacc[nt][0] *= f0; oacc[nt][1] *= f0;
                oacc[nt][2] *= f1; oacc[nt][3] *= f1;
            }

            // ---- O += P V ----
#pragma unroll
            for (int ks = 0; ks < 4; ++ks) {
                if (kb0 + ks * 16 > wlast) break;      // P identically 0 there
                uint32_t ah[4] = { ph[2 * ks][0], ph[2 * ks][1],
                                   ph[2 * ks + 1][0], ph[2 * ks + 1][1] };
                uint32_t al[4] = { pl[2 * ks][0], pl[2 * ks][1],
                                   pl[2 * ks + 1][0], pl[2 * ks + 1][1] };
#pragma unroll
                for (int dnt = 0; dnt < 4; ++dnt) {
                    uint32_t vh[4], vl[4];
                    uint32_t ad = st + 2u * KVT_BYTES
                                + (uint32_t)(ks * 16) * AROWB
                                + a_ro + (uint32_t)dnt * 32u;
                    ldsm4t(vh, ad);
                    ldsm4t(vl, ad + KVT_BYTES);
#pragma unroll
                    for (int hf = 0; hf < 2; ++hf) {
                        float* d = oacc[dnt * 2 + hf];
                        mma16816(d, ah, vh + hf * 2);
                        mma16816(d, al, vh + hf * 2);
                        mma16816(d, ah, vl + hf * 2);
                    }
                }
            }
        }
    }

    // ---- epilogue ----
    const int bb = bh >> 4;
    const int h  = bh & 15;
    const float inv0 = 1.0f / l0r;
    const float inv1 = 1.0f / l1r;
    const int t0 = q0 + warp_m + qrow;
#pragma unroll
    for (int nt = 0; nt < 8; ++nt) {
        const int d = nt * 8 + qcol;
        uint32_t hi, lo;
        size_t i0 = (size_t)(bb * T_ + t0) * D_ + h * HD_ + d;
        split2(oacc[nt][0] * inv0, oacc[nt][1] * inv0, hi, lo);
        *(uint32_t*)(g_oh + i0) = hi;
        *(uint32_t*)(g_ol + i0) = lo;
        size_t i1 = (size_t)(bb * T_ + t0 + 8) * D_ + h * HD_ + d;
        split2(oacc[nt][2] * inv1, oacc[nt][3] * inv1, hi, lo);
        *(uint32_t*)(g_oh + i1) = hi;
        *(uint32_t*)(g_ol + i1) = lo;
    }
}

// ---------------------------------------------------------------------------
// kernel_launch
// ---------------------------------------------------------------------------
extern "C" void kernel_launch(void* const* d_in, const int* in_sizes, int n_in,
                              void* d_out, int out_size)
{
    (void)in_sizes; (void)n_in; (void)out_size;
    const float* x     = (const float*)d_in[0];
    const float* Wqkv  = (const float*)d_in[1];
    const float* bqkv  = (const float*)d_in[2];
    const float* Wproj = (const float*)d_in[3];
    const float* bproj = (const float*)d_in[4];
    float* out = (float*)d_out;

    cudaFuncSetAttribute(gemm_wm<0>,
                         cudaFuncAttributeMaxDynamicSharedMemorySize, GEMM_SMEM);
    cudaFuncSetAttribute(gemm_wm<1>,
                         cudaFuncAttributeMaxDynamicSharedMemorySize, GEMM_SMEM);
    cudaFuncSetAttribute(attn_wm,
                         cudaFuncAttributeMaxDynamicSharedMemorySize, ATT_SMEM);

    split_all<<<(SPLIT_TOTAL / 4 + 255) / 256, 256>>>(x, Wqkv, Wproj);

    gemm_wm<0><<<dim3(NQKV / 128, M_ / 128), 256, GEMM_SMEM>>>(bqkv, nullptr);

    attn_wm<<<dim3(T_ / 128, B_ * H_), 256, ATT_SMEM>>>();

    gemm_wm<1><<<dim3(D_ / 128, M_ / 128), 256, GEMM_SMEM>>>(bproj, out);
}

// round 16
// speedup vs baseline: 1.0696x; 1.0143x over previous
#include <cuda_runtime.h>
#include <cuda_bf16.h>
#include <cstdint>

// Problem constants
#define B_   2
#define T_   2048
#define D_   1024
#define H_   16
#define HD_  64
#define M_   (B_ * T_)       // 4096
#define NQKV (3 * D_)        // 3072
#define K_   D_              // 1024

// ---------------------------------------------------------------------------
// Scratch (__device__ globals: allocation-free rule)
// ---------------------------------------------------------------------------
__device__ __nv_bfloat16 g_xh[M_ * D_],    g_xl[M_ * D_];
__device__ __nv_bfloat16 g_wqh[NQKV * D_], g_wql[NQKV * D_];
__device__ __nv_bfloat16 g_wph[D_ * D_],   g_wpl[D_ * D_];
__device__ __nv_bfloat16 g_Qh[M_ * D_], g_Ql[M_ * D_];
__device__ __nv_bfloat16 g_Kh[M_ * D_], g_Kl[M_ * D_];
__device__ __nv_bfloat16 g_Vh[M_ * D_], g_Vl[M_ * D_];
__device__ __nv_bfloat16 g_oh[M_ * D_], g_ol[M_ * D_];

// ---------------------------------------------------------------------------
// Base-ISA tensor-core helpers (compute_103-safe: NO tcgen05)
// ---------------------------------------------------------------------------
__device__ __forceinline__ uint32_t smem_to_u32(const void* p) {
    uint32_t a;
    asm("{ .reg .u64 t; cvta.to.shared.u64 t, %1; cvt.u32.u64 %0, t; }"
        : "=r"(a) : "l"(p));
    return a;
}
__device__ __forceinline__ void ldsm4(uint32_t* r, uint32_t addr) {
    asm volatile("ldmatrix.sync.aligned.m8n8.x4.shared.b16 {%0,%1,%2,%3}, [%4];"
        : "=r"(r[0]), "=r"(r[1]), "=r"(r[2]), "=r"(r[3]) : "r"(addr));
}
__device__ __forceinline__ void ldsm4t(uint32_t* r, uint32_t addr) {
    asm volatile("ldmatrix.sync.aligned.m8n8.x4.trans.shared.b16 {%0,%1,%2,%3}, [%4];"
        : "=r"(r[0]), "=r"(r[1]), "=r"(r[2]), "=r"(r[3]) : "r"(addr));
}
__device__ __forceinline__ void mma16816(float* d, const uint32_t* a, const uint32_t* b) {
    asm volatile(
        "mma.sync.aligned.m16n8k16.row.col.f32.bf16.bf16.f32 "
        "{%0,%1,%2,%3}, {%4,%5,%6,%7}, {%8,%9}, {%0,%1,%2,%3};"
        : "+f"(d[0]), "+f"(d[1]), "+f"(d[2]), "+f"(d[3])
        : "r"(a[0]), "r"(a[1]), "r"(a[2]), "r"(a[3]), "r"(b[0]), "r"(b[1]));
}
#define CP_ASYNC16(s, g) \
    asm volatile("cp.async.cg.shared.global [%0], [%1], 16;" :: "r"(s), "l"(g))
#define CP_COMMIT() asm volatile("cp.async.commit_group;" ::: "memory")
#define CP_WAIT1()  asm volatile("cp.async.wait_group 1;" ::: "memory")
#define CP_WAIT0()  asm volatile("cp.async.wait_group 0;" ::: "memory")

__device__ __forceinline__ void split2(float x, float y, uint32_t& hi, uint32_t& lo) {
    __nv_bfloat16 hx = __float2bfloat16(x), hy = __float2bfloat16(y);
    __nv_bfloat162 hv(hx, hy);
    __nv_bfloat162 lv(__float2bfloat16(x - __bfloat162float(hx)),
                      __float2bfloat16(y - __bfloat162float(hy)));
    hi = *reinterpret_cast<uint32_t*>(&hv);
    lo = *reinterpret_cast<uint32_t*>(&lv);
}

// ---------------------------------------------------------------------------
// Merged fp32 -> bf16 hi/lo split: one launch covers x | W_qkv | W_proj.
// ---------------------------------------------------------------------------
#define XN   (M_ * D_)          // 4194304
#define WQN  (NQKV * D_)        // 3145728
#define WPN  (D_ * D_)          // 1048576
#define SPLIT_TOTAL (XN + WQN + WPN)

__global__ __launch_bounds__(256)
void split_all(const float* __restrict__ x, const float* __restrict__ wq,
               const float* __restrict__ wp)
{
    int i = (blockIdx.x * 256 + threadIdx.x) * 4;
    if (i >= SPLIT_TOTAL) return;

    const float* src;
    __nv_bfloat16 *h, *l;
    int off;
    if (i < XN)            { src = x;  h = g_xh;  l = g_xl;  off = i; }
    else if (i < XN + WQN) { src = wq; h = g_wqh; l = g_wql; off = i - XN; }
    else                   { src = wp; h = g_wph; l = g_wpl; off = i - XN - WQN; }

    float4 v = *(const float4*)(src + off);
    uint32_t h0, l0, h1, l1;
    split2(v.x, v.y, h0, l0);
    split2(v.z, v.w, h1, l1);
    uint32_t* hp = (uint32_t*)(h + off);
    uint32_t* lp = (uint32_t*)(l + off);
    hp[0] = h0; hp[1] = h1;
    lp[0] = l0; lp[1] = l1;
}

// ---------------------------------------------------------------------------
// Warp-MMA GEMM (HMMA bf16, 3-term split): C = A @ W^T + bias.
// R15: single-sync pipeline (wait -> sync -> prefetch -> compute) and
// term-major MMA passes (per-accumulator order unchanged: hh, hl, lh).
// ---------------------------------------------------------------------------
#define ROWB        80u
#define TILE_BYTES  (128u * ROWB)
#define STAGE_BYTES (4u * TILE_BYTES)
#define GEMM_SMEM   (2 * (int)STAGE_BYTES)
#define NCH         (K_ / 32)

__device__ __forceinline__ void load_stage(
    uint32_t sbase,
    const __nv_bfloat16* __restrict__ Ah, const __nv_bfloat16* __restrict__ Al,
    const __nv_bfloat16* __restrict__ Bh, const __nv_bfloat16* __restrict__ Bl,
    int m0, int n0, int k0, int tid)
{
#pragma unroll
    for (int i = 0; i < 8; ++i) {
        const int arr = i >> 1;
        const int row = ((i & 1) << 6) + (tid >> 2);
        const int ck  = tid & 3;
        const __nv_bfloat16* src = (arr == 0) ? Ah : (arr == 1) ? Al
                                  : (arr == 2) ? Bh : Bl;
        const int grow = ((arr < 2) ? m0 : n0) + row;
        const void* g = (const char*)(src + (size_t)grow * K_ + k0) + ck * 16;
        uint32_t s = sbase + (uint32_t)arr * TILE_BYTES
                           + (uint32_t)row * ROWB + (uint32_t)ck * 16u;
        CP_ASYNC16(s, g);
    }
}

template <int MODE>
__global__ __launch_bounds__(256, 2)
void gemm_wm(const float* __restrict__ bias, float* __restrict__ out)
{
    extern __shared__ char smem[];

    const __nv_bfloat16* Ah = (MODE == 0) ? g_xh  : g_oh;
    const __nv_bfloat16* Al = (MODE == 0) ? g_xl  : g_ol;
    const __nv_bfloat16* Bh = (MODE == 0) ? g_wqh : g_wph;
    const __nv_bfloat16* Bl = (MODE == 0) ? g_wql : g_wpl;

    const int tid    = threadIdx.x;
    const int wid    = tid >> 5;
    const int lane   = tid & 31;
    const int m0     = blockIdx.y << 7;
    const int n0     = blockIdx.x << 7;
    const int warp_m = (wid >> 1) * 32;
    const int warp_n = (wid & 1) * 64;
    const uint32_t sb = smem_to_u32(smem);

    const int sub = lane >> 3, rin = lane & 7;
    const uint32_t a_ro = (uint32_t)((sub & 1) * 8 + rin) * ROWB
                        + (uint32_t)(sub >> 1) * 16u;
    const uint32_t b_ro = (uint32_t)((sub >> 1) * 8 + rin) * ROWB
                        + (uint32_t)(sub & 1) * 16u;

    float acc[2][8][4];
#pragma unroll
    for (int mt = 0; mt < 2; ++mt)
#pragma unroll
        for (int nt = 0; nt < 8; ++nt)
#pragma unroll
            for (int q = 0; q < 4; ++q) acc[mt][nt][q] = 0.f;

    load_stage(sb, Ah, Al, Bh, Bl, m0, n0, 0, tid);
    CP_COMMIT();

    for (int ch = 0; ch < NCH; ++ch) {
        const uint32_t st = sb + (uint32_t)(ch & 1) * STAGE_BYTES;
        CP_WAIT0();                 // chunk ch resident (only pending group)
        __syncthreads();            // visible to all + other buffer free
        if (ch + 1 < NCH) {
            load_stage(sb + (uint32_t)((ch + 1) & 1) * STAGE_BYTES,
                       Ah, Al, Bh, Bl, m0, n0, (ch + 1) * 32, tid);
            CP_COMMIT();            // lands while we compute chunk ch
        }

#pragma unroll
        for (int ks = 0; ks < 2; ++ks) {
            uint32_t ah[2][4], alr[2][4];
#pragma unroll
            for (int mt = 0; mt < 2; ++mt) {
                uint32_t ab = st + (uint32_t)(warp_m + mt * 16) * ROWB
                                 + a_ro + (uint32_t)ks * 32u;
                ldsm4(ah[mt],  ab);
                ldsm4(alr[mt], ab + TILE_BYTES);
            }
#pragma unroll
            for (int ng = 0; ng < 4; ++ng) {
                uint32_t bh[4], blr[4];
                uint32_t bbadr = st + 2u * TILE_BYTES
                               + (uint32_t)(warp_n + ng * 16) * ROWB
                               + b_ro + (uint32_t)ks * 32u;
                ldsm4(bh,  bbadr);
                ldsm4(blr, bbadr + TILE_BYTES);
                // term-major passes; per-accumulator order stays hh, hl, lh
#pragma unroll
                for (int mt = 0; mt < 2; ++mt)
#pragma unroll
                    for (int hf = 0; hf < 2; ++hf)
                        mma16816(acc[mt][ng * 2 + hf], ah[mt],  bh  + hf * 2);
#pragma unroll
                for (int mt = 0; mt < 2; ++mt)
#pragma unroll
                    for (int hf = 0; hf < 2; ++hf)
                        mma16816(acc[mt][ng * 2 + hf], ah[mt],  blr + hf * 2);
#pragma unroll
                for (int mt = 0; mt < 2; ++mt)
#pragma unroll
                    for (int hf = 0; hf < 2; ++hf)
                        mma16816(acc[mt][ng * 2 + hf], alr[mt], bh  + hf * 2);
            }
        }
    }

    const int qrow = lane >> 2;
    const int qcol = (lane & 3) * 2;
#pragma unroll
    for (int mt = 0; mt < 2; ++mt)
#pragma unroll
        for (int rr = 0; rr < 2; ++rr) {
            const int m  = m0 + warp_m + mt * 16 + qrow + rr * 8;
            const int bb = m >> 11;
            const int t  = m & (T_ - 1);
#pragma unroll
            for (int nt = 0; nt < 8; ++nt) {
                const int n = n0 + warp_n + nt * 8 + qcol;
                float vx = acc[mt][nt][rr * 2 + 0] + bias[n];
                float vy = acc[mt][nt][rr * 2 + 1] + bias[n + 1];
                if (MODE == 0) {
                    const int part = n >> 10;       // 0=Q 1=K 2=V
                    const int c    = n & (D_ - 1);
                    const int h    = c >> 6;
                    const int d    = c & (HD_ - 1);
                    __nv_bfloat16 *dh, *dl;
                    if      (part == 0) { dh = g_Qh; dl = g_Ql; }
                    else if (part == 1) { dh = g_Kh; dl = g_Kl; }
                    else                { dh = g_Vh; dl = g_Vl; }
                    size_t idx = ((size_t)(bb * H_ + h) * T_ + t) * HD_ + d;
                    uint32_t hi, lo;
                    split2(vx, vy, hi, lo);
                    *(uint32_t*)(dh + idx) = hi;
                    *(uint32_t*)(dl + idx) = lo;
                } else {
                    float2 v; v.x = vx; v.y = vy;
                    *(float2*)(out + (size_t)m * D_ + n) = v;
                }
            }
        }
}

// ---------------------------------------------------------------------------
// HMMA flash-attention (causal) — R7 structure with the single-sync pipeline.
// 128 queries/CTA of one (b,h), 8 warps x 16 rows, KV blocks of 64,
// cp.async double-buffered, 3-term bf16 split, causal tile-skipping.
// ---------------------------------------------------------------------------
#define AROWB        144u
#define Q_TILE_BYTES (128u * AROWB)     // 18432
#define KVT_BYTES    (64u * AROWB)      // 9216
#define ATT_STAGE    (4u * KVT_BYTES)   // 36864
#define ATT_SMEM     (int)(2u * Q_TILE_BYTES + 2u * ATT_STAGE)  // 110592

__device__ __forceinline__ void attn_load_kv(uint32_t sk, size_t base, int kb0, int tid)
{
#pragma unroll
    for (int i = 0; i < 8; ++i) {
        const int arr = i >> 1;                     // 0 Kh,1 Kl,2 Vh,3 Vl
        const int row = ((i & 1) << 5) + (tid >> 3);
        const int ck  = tid & 7;
        const __nv_bfloat16* src = (arr == 0) ? g_Kh : (arr == 1) ? g_Kl
                                  : (arr == 2) ? g_Vh : g_Vl;
        const void* g = src + base + (size_t)(kb0 + row) * HD_ + ck * 8;
        uint32_t s = sk + (uint32_t)arr * KVT_BYTES
                        + (uint32_t)row * AROWB + (uint32_t)ck * 16u;
        CP_ASYNC16(s, g);
    }
}

__global__ __launch_bounds__(256)
void attn_wm()
{
    extern __shared__ char smem[];
    const uint32_t sb   = smem_to_u32(smem);
    const uint32_t sQ   = sb;
    const uint32_t sKV0 = sb + 2u * Q_TILE_BYTES;

    const int tid    = threadIdx.x;
    const int wid    = tid >> 5;
    const int lane   = tid & 31;
    const int qb     = (int)gridDim.x - 1 - (int)blockIdx.x;   // heavy first
    const int bh     = blockIdx.y;
    const int q0     = qb << 7;
    const size_t base = (size_t)bh * (T_ * HD_);
    const int warp_m = wid * 16;
    const int nblk   = 2 * (qb + 1);
    const int wlast  = q0 + warp_m + 15;    // last valid col for this warp
    const float scale = 0.125f;

    const int sub = lane >> 3, rin = lane & 7;
    const uint32_t a_ro = (uint32_t)((sub & 1) * 8 + rin) * AROWB
                        + (uint32_t)(sub >> 1) * 16u;
    const uint32_t b_ro = (uint32_t)((sub >> 1) * 8 + rin) * AROWB
                        + (uint32_t)(sub & 1) * 16u;

#pragma unroll
    for (int i = 0; i < 8; ++i) {
        const int arr = i >> 2;                     // 0 Qh, 1 Ql
        const int row = ((i & 3) << 5) + (tid >> 3);
        const int ck  = tid & 7;
        const __nv_bfloat16* src = arr ? g_Ql : g_Qh;
        const void* g = src + base + (size_t)(q0 + row) * HD_ + ck * 8;
        uint32_t s = sQ + (uint32_t)arr * Q_TILE_BYTES
                        + (uint32_t)row * AROWB + (uint32_t)ck * 16u;
        CP_ASYNC16(s, g);
    }
    CP_COMMIT();                        // group: Q
    attn_load_kv(sKV0, base, 0, tid);   // KV block 0 -> buffer 0
    CP_COMMIT();                        // group: KV0
    CP_WAIT1();                         // Q complete (KV0 may be in flight)
    __syncthreads();

    uint32_t qh[4][4], ql[4][4];
#pragma unroll
    for (int ks = 0; ks < 4; ++ks) {
        uint32_t ab = sQ + (uint32_t)warp_m * AROWB + a_ro + (uint32_t)ks * 32u;
        ldsm4(qh[ks], ab);
        ldsm4(ql[ks], ab + Q_TILE_BYTES);
    }

    float oacc[8][4];
#pragma unroll
    for (int nt = 0; nt < 8; ++nt)
#pragma unroll
        for (int q = 0; q < 4; ++q) oacc[nt][q] = 0.f;
    float m0r = -1e30f, m1r = -1e30f, l0r = 0.f, l1r = 0.f;

    const int qrow = lane >> 2;
    const int qcol = (lane & 3) * 2;
    const int rg0  = q0 + warp_m + qrow;

    for (int jb = 0; jb < nblk; ++jb) {
        const uint32_t st = sKV0 + (uint32_t)(jb & 1) * ATT_STAGE;
        const int kb0 = jb << 6;
        CP_WAIT0();                     // KV block jb resident
        __syncthreads();                // visible + other buffer free
        if (jb + 1 < nblk) {
            attn_load_kv(sKV0 + (uint32_t)((jb + 1) & 1) * ATT_STAGE,
                         base, (jb + 1) << 6, tid);
            CP_COMMIT();                // lands while we compute block jb
        }

        const bool block_dead = (kb0 > wlast);
        if (!block_dead) {
            // ---- S = Q K^T ----
            float s[8][4];
#pragma unroll
            for (int nt = 0; nt < 8; ++nt)
#pragma unroll
                for (int q = 0; q < 4; ++q) s[nt][q] = 0.f;

#pragma unroll
            for (int ntile = 0; ntile < 4; ++ntile) {
                if (kb0 + ntile * 16 > wlast) break;   // warp-uniform causal skip
#pragma unroll
                for (int ks = 0; ks < 4; ++ks) {
                    uint32_t kh[4], kl[4];
                    uint32_t ad = st + (uint32_t)(ntile * 16) * AROWB
                                     + b_ro + (uint32_t)ks * 32u;
                    ldsm4(kh, ad);
                    ldsm4(kl, ad + KVT_BYTES);
                    // term-major; per-accumulator order: qh*kh, qh*kl, ql*kh
#pragma unroll
                    for (int hf = 0; hf < 2; ++hf)
                        mma16816(s[ntile * 2 + hf], qh[ks], kh + hf * 2);
#pragma unroll
                    for (int hf = 0; hf < 2; ++hf)
                        mma16816(s[ntile * 2 + hf], qh[ks], kl + hf * 2);
#pragma unroll
                    for (int hf = 0; hf < 2; ++hf)
                        mma16816(s[ntile * 2 + hf], ql[ks], kh + hf * 2);
                }
            }

            // ---- causal mask (near-diagonal blocks) ----
            if (kb0 + 63 > q0 + warp_m) {
#pragma unroll
                for (int nt = 0; nt < 8; ++nt) {
                    int cg = kb0 + nt * 8 + qcol;
                    if (cg     > rg0)     s[nt][0] = -1e30f;
                    if (cg + 1 > rg0)     s[nt][1] = -1e30f;
                    if (cg     > rg0 + 8) s[nt][2] = -1e30f;
                    if (cg + 1 > rg0 + 8) s[nt][3] = -1e30f;
                }
            }

            // ---- online softmax ----
            float mx0 = -1e30f, mx1 = -1e30f;
#pragma unroll
            for (int nt = 0; nt < 8; ++nt) {
                mx0 = fmaxf(mx0, fmaxf(s[nt][0], s[nt][1]));
                mx1 = fmaxf(mx1, fmaxf(s[nt][2], s[nt][3]));
            }
            mx0 = fmaxf(mx0, __shfl_xor_sync(0xffffffffu, mx0, 1));
            mx0 = fmaxf(mx0, __shfl_xor_sync(0xffffffffu, mx0, 2));
            mx1 = fmaxf(mx1, __shfl_xor_sync(0xffffffffu, mx1, 1));
            mx1 = fmaxf(mx1, __shfl_xor_sync(0xffffffffu, mx1, 2));
            float mn0 = fmaxf(m0r, mx0 * scale);
            float mn1 = fmaxf(m1r, mx1 * scale);

            uint32_t ph[8][2], pl[8][2];
            float sum0 = 0.f, sum1 = 0.f;
#pragma unroll
            for (int nt = 0; nt < 8; ++nt) {
                float p0 = __expf(fmaf(s[nt][0], scale, -mn0));
                float p1 = __expf(fmaf(s[nt][1], scale, -mn0));
                float p2 = __expf(fmaf(s[nt][2], scale, -mn1));
                float p3 = __expf(fmaf(s[nt][3], scale, -mn1));
                sum0 += p0 + p1;
                sum1 += p2 + p3;
                split2(p0, p1, ph[nt][0], pl[nt][0]);
                split2(p2, p3, ph[nt][1], pl[nt][1]);
            }
            sum0 += __shfl_xor_sync(0xffffffffu, sum0, 1);
            sum0 += __shfl_xor_sync(0xffffffffu, sum0, 2);
            sum1 += __shfl_xor_sync(0xffffffffu, sum1, 1);
            sum1 += __shfl_xor_sync(0xffffffffu, sum1, 2);

            float f0 = __expf(m0r - mn0);
            float f1 = __expf(m1r - mn1);
            l0r = l0r * f0 + sum0;
            l1r = l1r * f1 + sum1;
            m0r = mn0; m1r = mn1;
#pragma unroll
            for (int nt = 0; nt < 8; ++nt) {
                oacc[nt][0] *= f0; oacc[nt][1] *= f0;
                oacc[nt][2] *= f1; oacc[nt][3] *= f1;
            }

            // ---- O += P V ----
#pragma unroll
            for (int ks = 0; ks < 4; ++ks) {
                if (kb0 + ks * 16 > wlast) break;      // P identically 0 there
                uint32_t ah[4] = { ph[2 * ks][0], ph[2 * ks][1],
                                   ph[2 * ks + 1][0], ph[2 * ks + 1][1] };
                uint32_t al[4] = { pl[2 * ks][0], pl[2 * ks][1],
                                   pl[2 * ks + 1][0], pl[2 * ks + 1][1] };
#pragma unroll
                for (int dnt = 0; dnt < 4; ++dnt) {
                    uint32_t vh[4], vl[4];
                    uint32_t ad = st + 2u * KVT_BYTES
                                + (uint32_t)(ks * 16) * AROWB
                                + a_ro + (uint32_t)dnt * 32u;
                    ldsm4t(vh, ad);
                    ldsm4t(vl, ad + KVT_BYTES);
                    // term-major; per-accumulator order: ah*vh, al*vh, ah*vl
#pragma unroll
                    for (int hf = 0; hf < 2; ++hf)
                        mma16816(oacc[dnt * 2 + hf], ah, vh + hf * 2);
#pragma unroll
                    for (int hf = 0; hf < 2; ++hf)
                        mma16816(oacc[dnt * 2 + hf], al, vh + hf * 2);
#pragma unroll
                    for (int hf = 0; hf < 2; ++hf)
                        mma16816(oacc[dnt * 2 + hf], ah, vl + hf * 2);
                }
            }
        }
    }

    // ---- epilogue ----
    const int bb = bh >> 4;
    const int h  = bh & 15;
    const float inv0 = 1.0f / l0r;
    const float inv1 = 1.0f / l1r;
    const int t0 = q0 + warp_m + qrow;
#pragma unroll
    for (int nt = 0; nt < 8; ++nt) {
        const int d = nt * 8 + qcol;
        uint32_t hi, lo;
        size_t i0 = (size_t)(bb * T_ + t0) * D_ + h * HD_ + d;
        split2(oacc[nt][0] * inv0, oacc[nt][1] * inv0, hi, lo);
        *(uint32_t*)(g_oh + i0) = hi;
        *(uint32_t*)(g_ol + i0) = lo;
        size_t i1 = (size_t)(bb * T_ + t0 + 8) * D_ + h * HD_ + d;
        split2(oacc[nt][2] * inv1, oacc[nt][3] * inv1, hi, lo);
        *(uint32_t*)(g_oh + i1) = hi;
        *(uint32_t*)(g_ol + i1) = lo;
    }
}

// ---------------------------------------------------------------------------
// kernel_launch
// ---------------------------------------------------------------------------
extern "C" void kernel_launch(void* const* d_in, const int* in_sizes, int n_in,
                              void* d_out, int out_size)
{
    (void)in_sizes; (void)n_in; (void)out_size;
    const float* x     = (const float*)d_in[0];
    const float* Wqkv  = (const float*)d_in[1];
    const float* bqkv  = (const float*)d_in[2];
    const float* Wproj = (const float*)d_in[3];
    const float* bproj = (const float*)d_in[4];
    float* out = (float*)d_out;

    cudaFuncSetAttribute(gemm_wm<0>,
                         cudaFuncAttributeMaxDynamicSharedMemorySize, GEMM_SMEM);
    cudaFuncSetAttribute(gemm_wm<1>,
                         cudaFuncAttributeMaxDynamicSharedMemorySize, GEMM_SMEM);
    cudaFuncSetAttribute(attn_wm,
                         cudaFuncAttributeMaxDynamicSharedMemorySize, ATT_SMEM);

    split_all<<<(SPLIT_TOTAL / 4 + 255) / 256, 256>>>(x, Wqkv, Wproj);

    gemm_wm<0><<<dim3(NQKV / 128, M_ / 128), 256, GEMM_SMEM>>>(bqkv, nullptr);

    attn_wm<<<dim3(T_ / 128, B_ * H_), 256, ATT_SMEM>>>();

    gemm_wm<1><<<dim3(D_ / 128, M_ / 128), 256, GEMM_SMEM>>>(bproj, out);
}